// round 3
// baseline (speedup 1.0000x reference)
#include <cuda_runtime.h>

// BehaviorEngine: per-pixel self-pattern + MLP(33->64 relu ->32) + alpha*g
// H=W=1024, D=32, HID=64. One thread per pixel, 128 threads/block.
// FP32 throughout; MLP inner products use packed fma.rn.f32x2 (SASS FFMA2).

#define HW_PIX   (1024*1024)
#define NTHREADS 128
#define EPSF     1e-8f
#define ALPHAF   0.3f
#define PATW     0.1f

__device__ __forceinline__ unsigned long long ffma2(unsigned long long a,
                                                    unsigned long long b,
                                                    unsigned long long c) {
    unsigned long long d;
    asm("fma.rn.f32x2 %0, %1, %2, %3;" : "=l"(d) : "l"(a), "l"(b), "l"(c));
    return d;
}
__device__ __forceinline__ unsigned long long pack_dup(float x) {
    unsigned long long d;
    asm("mov.b64 %0, {%1, %1};" : "=l"(d) : "f"(x));
    return d;
}
__device__ __forceinline__ unsigned long long pack2(float lo, float hi) {
    unsigned long long d;
    asm("mov.b64 %0, {%1, %2};" : "=l"(d) : "f"(lo), "f"(hi));
    return d;
}
__device__ __forceinline__ void unpack2(unsigned long long v, float& lo, float& hi) {
    asm("mov.b64 {%0, %1}, %2;" : "=f"(lo), "=f"(hi) : "l"(v));
}

__global__ void __launch_bounds__(NTHREADS)
be_kernel(const float* __restrict__ grid, const float* __restrict__ pot,
          const float* __restrict__ W1,   const float* __restrict__ b1,
          const float* __restrict__ W2,   const float* __restrict__ b2,
          float* __restrict__ out)
{
    __shared__ __align__(16) float sW1[33 * 64];   // [c][f], f contiguous
    __shared__ __align__(16) float sW2[64 * 32];   // [f][d], d contiguous
    __shared__ __align__(16) float sB1[64];
    __shared__ __align__(16) float sB2[32];
    __shared__ float sX[NTHREADS * 33];            // per-thread x vec, stride 33 (conflict-free)

    const int tid = threadIdx.x;

    // Cooperative weight staging
    for (int i = tid; i < 33 * 64; i += NTHREADS) sW1[i] = W1[i];
    for (int i = tid; i < 64 * 32; i += NTHREADS) sW2[i] = W2[i];
    if (tid < 64) sB1[tid] = b1[tid];
    if (tid < 32) sB2[tid] = b2[tid];

    const size_t p = (size_t)blockIdx.x * NTHREADS + tid;
    const float4* g4 = (const float4*)(grid + p * 32);
    float4 gv[8];
    #pragma unroll
    for (int k = 0; k < 8; k++) gv[k] = g4[k];      // LDG overlaps the barrier
    const float potv = pot[p];

    __syncthreads();

    float g[32];
    #pragma unroll
    for (int k = 0; k < 8; k++) {
        g[4 * k + 0] = gv[k].x; g[4 * k + 1] = gv[k].y;
        g[4 * k + 2] = gv[k].z; g[4 * k + 3] = gv[k].w;
    }

    // norms: ||g|| and ||g^3||
    float gn2 = 0.f, cn2 = 0.f;
    #pragma unroll
    for (int i = 0; i < 32; i++) {
        float q  = g[i] * g[i];
        gn2 += q;
        float c3 = q * g[i];
        cn2 = fmaf(c3, c3, cn2);
    }
    const float t = PATW * sqrtf(gn2) / (sqrtf(cn2) + EPSF);

    // x = g + t*g^3 -> shared stage;  out-acc pre-init with b2 + alpha*g
    float* myX = sX + tid * 33;
    unsigned long long oacc[16];
    #pragma unroll
    for (int i = 0; i < 32; i += 2) {
        float q0 = g[i] * g[i];
        float q1 = g[i + 1] * g[i + 1];
        myX[i]     = fmaf(t * q0, g[i],     g[i]);
        myX[i + 1] = fmaf(t * q1, g[i + 1], g[i + 1]);
        oacc[i >> 1] = pack2(fmaf(ALPHAF, g[i],     sB2[i]),
                             fmaf(ALPHAF, g[i + 1], sB2[i + 1]));
    }
    myX[32] = potv;

    // Layer 1: h[64] = relu(x . W1 + b1), h kept as 32 packed f32x2 accumulators
    unsigned long long h2[32];
    const unsigned long long* b1p = (const unsigned long long*)sB1;
    #pragma unroll
    for (int j = 0; j < 32; j++) h2[j] = b1p[j];

    #pragma unroll 1
    for (int c = 0; c < 33; c++) {
        const unsigned long long xc2 = pack_dup(myX[c]);       // broadcast-free scalar LDS
        const ulonglong2* wr = (const ulonglong2*)(sW1 + c * 64);
        #pragma unroll
        for (int j = 0; j < 16; j++) {
            ulonglong2 w = wr[j];                              // LDS.128 (warp broadcast)
            h2[2 * j]     = ffma2(xc2, w.x, h2[2 * j]);
            h2[2 * j + 1] = ffma2(xc2, w.y, h2[2 * j + 1]);
        }
    }

    // Layer 2: out[32] += relu(h) . W2   (f-loop fully unrolled; h stays in regs)
    #pragma unroll
    for (int j = 0; j < 32; j++) {
        float lo, hi;
        unpack2(h2[j], lo, hi);
        lo = fmaxf(lo, 0.f);
        hi = fmaxf(hi, 0.f);
        {
            const unsigned long long hl = pack_dup(lo);
            const ulonglong2* wr = (const ulonglong2*)(sW2 + (2 * j) * 32);
            #pragma unroll
            for (int q = 0; q < 8; q++) {
                ulonglong2 w = wr[q];
                oacc[2 * q]     = ffma2(hl, w.x, oacc[2 * q]);
                oacc[2 * q + 1] = ffma2(hl, w.y, oacc[2 * q + 1]);
            }
        }
        {
            const unsigned long long hh = pack_dup(hi);
            const ulonglong2* wr = (const ulonglong2*)(sW2 + (2 * j + 1) * 32);
            #pragma unroll
            for (int q = 0; q < 8; q++) {
                ulonglong2 w = wr[q];
                oacc[2 * q]     = ffma2(hh, w.x, oacc[2 * q]);
                oacc[2 * q + 1] = ffma2(hh, w.y, oacc[2 * q + 1]);
            }
        }
    }

    float4* o4 = (float4*)(out + p * 32);
    #pragma unroll
    for (int k = 0; k < 8; k++) {
        float a, b, c, d;
        unpack2(oacc[2 * k],     a, b);
        unpack2(oacc[2 * k + 1], c, d);
        o4[k] = make_float4(a, b, c, d);
    }
}

extern "C" void kernel_launch(void* const* d_in, const int* in_sizes, int n_in,
                              void* d_out, int out_size) {
    const float* grid = (const float*)d_in[0];
    const float* pot  = (const float*)d_in[1];
    const float* W1   = (const float*)d_in[2];
    const float* b1   = (const float*)d_in[3];
    const float* W2   = (const float*)d_in[4];
    const float* b2   = (const float*)d_in[5];
    float* out = (float*)d_out;

    const int blocks = HW_PIX / NTHREADS;   // 8192
    be_kernel<<<blocks, NTHREADS>>>(grid, pot, W1, b1, W2, b2, out);
}

// round 5
// speedup vs baseline: 2.9598x; 2.9598x over previous
#include <cuda_runtime.h>
#include <cstdint>

#define ALPHAF 0.3f
#define EPSF   1e-8f
#define PATW   0.1f

// ---- dynamic smem layout (bytes) ----
#define O_X    0        // X staging: 128 rows x 72 halfs (144B stride) = 18432
#define O_B1   18432    // B1 image: 64 rows x 72 halfs  (wh|wl cols 0..63) = 9216
#define O_B2   27648    // B2 image: 32 rows x 136 halfs (wh|wl cols 0..127) = 8704
#define O_G    36352    // grid tile fp32: 128 x 33 = 16896
#define O_P    53248    // pot: 128 f32 = 512
#define O_B1S  53760    // b1: 64 f32
#define O_W1P  54016    // W1[32][:]: 64 f32
#define O_B2S  54272    // b2: 32 f32
#define SMEMSZ 54400

#define XSTR 72   // halfs
#define B1STR 72
#define B2STR 136

static __device__ __forceinline__ void ldm4(uint32_t* r, uint32_t addr) {
    asm volatile("ldmatrix.sync.aligned.m8n8.x4.shared.b16 {%0,%1,%2,%3}, [%4];"
                 : "=r"(r[0]), "=r"(r[1]), "=r"(r[2]), "=r"(r[3]) : "r"(addr));
}
static __device__ __forceinline__ void mma16816(float* c, const uint32_t* a, const uint32_t* b) {
    asm volatile(
        "mma.sync.aligned.m16n8k16.row.col.f32.bf16.bf16.f32 "
        "{%0,%1,%2,%3},{%4,%5,%6,%7},{%8,%9},{%0,%1,%2,%3};"
        : "+f"(c[0]), "+f"(c[1]), "+f"(c[2]), "+f"(c[3])
        : "r"(a[0]), "r"(a[1]), "r"(a[2]), "r"(a[3]), "r"(b[0]), "r"(b[1]));
}
static __device__ __forceinline__ unsigned short bfbits(float v) {
    unsigned short r;
    asm("cvt.rn.bf16.f32 %0, %1;" : "=h"(r) : "f"(v));
    return r;
}
static __device__ __forceinline__ float bf2f(unsigned short b) {
    return __uint_as_float((uint32_t)b << 16);
}
static __device__ __forceinline__ uint32_t packbf2(float lo, float hi) {
    uint32_t r;
    asm("cvt.rn.bf16x2.f32 %0, %1, %2;" : "=r"(r) : "f"(hi), "f"(lo));
    return r;
}

__global__ void __launch_bounds__(128)
be_mma(const float* __restrict__ grid, const float* __restrict__ pot,
       const float* __restrict__ W1,   const float* __restrict__ b1,
       const float* __restrict__ W2,   const float* __restrict__ b2,
       float* __restrict__ out)
{
    extern __shared__ __align__(16) unsigned char sm[];
    float* gsm          = (float*)(sm + O_G);
    float* psm          = (float*)(sm + O_P);
    float* b1s          = (float*)(sm + O_B1S);
    float* w1p          = (float*)(sm + O_W1P);
    float* b2s          = (float*)(sm + O_B2S);
    unsigned short* bt1 = (unsigned short*)(sm + O_B1);
    unsigned short* bt2 = (unsigned short*)(sm + O_B2);

    const int tid  = threadIdx.x;
    const int lane = tid & 31;
    const int w    = tid >> 5;

    const uint32_t xs_b = (uint32_t)__cvta_generic_to_shared(sm + O_X);
    const uint32_t b1_b = (uint32_t)__cvta_generic_to_shared(sm + O_B1);
    const uint32_t b2_b = (uint32_t)__cvta_generic_to_shared(sm + O_B2);

    // ---- stage grid tile (coalesced) into gsm[row][c], stride 33 ----
    {
        const uint4* gsrc = (const uint4*)(grid + (size_t)blockIdx.x * 4096);
        #pragma unroll
        for (int j = 0; j < 8; j++) {
            int e4 = tid + 128 * j;
            uint4 v = gsrc[e4];
            int row = e4 >> 3, c = (e4 & 7) * 4;
            float* d = gsm + row * 33 + c;
            d[0] = __uint_as_float(v.x); d[1] = __uint_as_float(v.y);
            d[2] = __uint_as_float(v.z); d[3] = __uint_as_float(v.w);
        }
    }
    psm[tid] = pot[(size_t)blockIdx.x * 128 + tid];

    // ---- build split weight images (B^T layout: [n][k], hi|lo halves) ----
    #pragma unroll
    for (int e = tid; e < 33 * 64; e += 128) {    // W1 rows 0..32
        int k = e >> 6, n = e & 63;
        float v = W1[e];
        if (k < 32) {
            unsigned short h = bfbits(v);
            bt1[n * B1STR + k]      = h;
            bt1[n * B1STR + 32 + k] = bfbits(v - bf2f(h));
        } else {
            w1p[n] = v;                            // potential row, fp32 exact
        }
    }
    #pragma unroll
    for (int e = tid; e < 64 * 32; e += 128) {     // W2
        int k = e >> 5, n = e & 31;
        float v = W2[e];
        unsigned short h = bfbits(v);
        bt2[n * B2STR + k]      = h;
        bt2[n * B2STR + 64 + k] = bfbits(v - bf2f(h));
    }
    if (tid < 64) b1s[tid] = b1[tid];
    if (tid < 32) b2s[tid] = b2[tid];
    __syncthreads();

    // ---- per-pixel x = g + 0.1 * g^3/(||g^3||+eps) * ||g||, split hi/lo ----
    {
        float gv[32];
        #pragma unroll
        for (int c = 0; c < 32; c++) gv[c] = gsm[tid * 33 + c];
        float gn2 = 0.f, cn2 = 0.f;
        #pragma unroll
        for (int i = 0; i < 32; i++) {
            float q = gv[i] * gv[i];
            gn2 += q;
            float c3 = q * gv[i];
            cn2 = fmaf(c3, c3, cn2);
        }
        const float t = PATW * sqrtf(gn2) / (sqrtf(cn2) + EPSF);
        uint32_t xh[16], xl[16];
        #pragma unroll
        for (int i = 0; i < 16; i++) {
            float x0 = fmaf(t * gv[2*i]   * gv[2*i],   gv[2*i],   gv[2*i]);
            float x1 = fmaf(t * gv[2*i+1] * gv[2*i+1], gv[2*i+1], gv[2*i+1]);
            uint32_t p = packbf2(x0, x1);
            xh[i] = p;
            float l0 = x0 - __uint_as_float(p << 16);
            float l1 = x1 - __uint_as_float(p & 0xFFFF0000u);
            xl[i] = packbf2(l0, l1);
        }
        uint4* xr = (uint4*)(sm + O_X + tid * (XSTR * 2));
        #pragma unroll
        for (int j = 0; j < 4; j++)
            xr[j] = make_uint4(xh[4*j], xh[4*j+1], xh[4*j+2], xh[4*j+3]);
        #pragma unroll
        for (int j = 0; j < 4; j++)
            xr[4 + j] = make_uint4(xl[4*j], xl[4*j+1], xl[4*j+2], xl[4*j+3]);
    }
    __syncwarp();

    const int m0 = w * 32;

    // ---- A fragments (xh cols 0..31, xl cols 32..63) ----
    uint32_t Ah[2][2][4], Al[2][2][4];
    #pragma unroll
    for (int mt = 0; mt < 2; mt++)
        #pragma unroll
        for (int ks = 0; ks < 2; ks++) {
            uint32_t base = xs_b + (uint32_t)(m0 + mt*16 + (lane & 15)) * (XSTR*2)
                          + ((lane >> 4) << 4);
            ldm4(Ah[mt][ks], base + (uint32_t)(ks*16) * 2);
            ldm4(Al[mt][ks], base + (uint32_t)(32 + ks*16) * 2);
        }

    // ---- B1 wh fragments ----
    uint32_t Bf[2][8][2];
    #pragma unroll
    for (int ks = 0; ks < 2; ks++)
        #pragma unroll
        for (int np = 0; np < 4; np++) {
            uint32_t a = b1_b + (uint32_t)(np*16 + ((lane>>4)<<3) + (lane&7)) * (B1STR*2)
                       + (uint32_t)(ks*16)*2 + (((lane>>3)&1) << 4);
            ldm4(&Bf[ks][2*np][0], a);
        }

    // ---- C1 init: b1[n] + pot[m]*W1[32][n] (fp32 exact) ----
    float C[2][8][4];
    const int nb = (lane & 3) * 2;
    float pv[2][2];
    #pragma unroll
    for (int mt = 0; mt < 2; mt++) {
        pv[mt][0] = psm[m0 + mt*16 + (lane >> 2)];
        pv[mt][1] = psm[m0 + mt*16 + (lane >> 2) + 8];
    }
    #pragma unroll
    for (int nt = 0; nt < 8; nt++) {
        int n = nt*8 + nb;
        float bb0 = b1s[n], bb1 = b1s[n+1], w0 = w1p[n], w1v = w1p[n+1];
        #pragma unroll
        for (int mt = 0; mt < 2; mt++) {
            C[mt][nt][0] = fmaf(pv[mt][0], w0,  bb0);
            C[mt][nt][1] = fmaf(pv[mt][0], w1v, bb1);
            C[mt][nt][2] = fmaf(pv[mt][1], w0,  bb0);
            C[mt][nt][3] = fmaf(pv[mt][1], w1v, bb1);
        }
    }

    // ---- GEMM1: xh*wh + xl*wh, then xh*wl ----
    #pragma unroll
    for (int ks = 0; ks < 2; ks++)
        #pragma unroll
        for (int mt = 0; mt < 2; mt++)
            #pragma unroll
            for (int nt = 0; nt < 8; nt++)
                mma16816(C[mt][nt], Ah[mt][ks], Bf[ks][nt]);
    #pragma unroll
    for (int ks = 0; ks < 2; ks++)
        #pragma unroll
        for (int mt = 0; mt < 2; mt++)
            #pragma unroll
            for (int nt = 0; nt < 8; nt++)
                mma16816(C[mt][nt], Al[mt][ks], Bf[ks][nt]);
    #pragma unroll
    for (int ks = 0; ks < 2; ks++)                 // reload B with wl (cols 32..63)
        #pragma unroll
        for (int np = 0; np < 4; np++) {
            uint32_t a = b1_b + (uint32_t)(np*16 + ((lane>>4)<<3) + (lane&7)) * (B1STR*2)
                       + (uint32_t)(32 + ks*16)*2 + (((lane>>3)&1) << 4);
            ldm4(&Bf[ks][2*np][0], a);
        }
    #pragma unroll
    for (int ks = 0; ks < 2; ks++)
        #pragma unroll
        for (int mt = 0; mt < 2; mt++)
            #pragma unroll
            for (int nt = 0; nt < 8; nt++)
                mma16816(C[mt][nt], Ah[mt][ks], Bf[ks][nt]);

    // ---- relu + split -> A2 fragments straight from C regs ----
    uint32_t Hh[2][4][4], Hl[2][4][4];
    #pragma unroll
    for (int mt = 0; mt < 2; mt++)
        #pragma unroll
        for (int ks = 0; ks < 4; ks++)
            #pragma unroll
            for (int q = 0; q < 4; q++) {
                int nt = 2*ks + (q >> 1);
                float hA = fmaxf(C[mt][nt][(q & 1) * 2],     0.f);
                float hB = fmaxf(C[mt][nt][(q & 1) * 2 + 1], 0.f);
                uint32_t p = packbf2(hA, hB);
                Hh[mt][ks][q] = p;
                float lA = hA - __uint_as_float(p << 16);
                float lB = hB - __uint_as_float(p & 0xFFFF0000u);
                Hl[mt][ks][q] = packbf2(lA, lB);
            }

    // ---- GEMM2: hh*w2h + hl*w2h, then hh*w2l ----
    float C2[2][4][4];
    #pragma unroll
    for (int mt = 0; mt < 2; mt++)
        #pragma unroll
        for (int nt = 0; nt < 4; nt++)
            #pragma unroll
            for (int q = 0; q < 4; q++) C2[mt][nt][q] = 0.f;

    uint32_t B2f[4][2];
    #pragma unroll
    for (int ks = 0; ks < 4; ks++) {
        #pragma unroll
        for (int np = 0; np < 2; np++) {
            uint32_t a = b2_b + (uint32_t)(np*16 + ((lane>>4)<<3) + (lane&7)) * (B2STR*2)
                       + (uint32_t)(ks*16)*2 + (((lane>>3)&1) << 4);
            ldm4(&B2f[2*np][0], a);
        }
        #pragma unroll
        for (int mt = 0; mt < 2; mt++)
            #pragma unroll
            for (int nt = 0; nt < 4; nt++) {
                mma16816(C2[mt][nt], Hh[mt][ks], B2f[nt]);
                mma16816(C2[mt][nt], Hl[mt][ks], B2f[nt]);
            }
    }
    #pragma unroll
    for (int ks = 0; ks < 4; ks++) {
        #pragma unroll
        for (int np = 0; np < 2; np++) {
            uint32_t a = b2_b + (uint32_t)(np*16 + ((lane>>4)<<3) + (lane&7)) * (B2STR*2)
                       + (uint32_t)(64 + ks*16)*2 + (((lane>>3)&1) << 4);
            ldm4(&B2f[2*np][0], a);
        }
        #pragma unroll
        for (int mt = 0; mt < 2; mt++)
            #pragma unroll
            for (int nt = 0; nt < 4; nt++)
                mma16816(C2[mt][nt], Hh[mt][ks], B2f[nt]);
    }

    // ---- epilogue: out = C2 + b2 + alpha*g ----
    float* outb = out + (size_t)blockIdx.x * 4096;
    #pragma unroll
    for (int mt = 0; mt < 2; mt++) {
        int r0 = m0 + mt*16 + (lane >> 2);
        int r1 = r0 + 8;
        #pragma unroll
        for (int nt = 0; nt < 4; nt++) {
            int n = nt*8 + nb;
            float bb0 = b2s[n], bb1 = b2s[n+1];
            float2 o0, o1;
            o0.x = fmaf(ALPHAF, gsm[r0*33 + n],     C2[mt][nt][0] + bb0);
            o0.y = fmaf(ALPHAF, gsm[r0*33 + n + 1], C2[mt][nt][1] + bb1);
            o1.x = fmaf(ALPHAF, gsm[r1*33 + n],     C2[mt][nt][2] + bb0);
            o1.y = fmaf(ALPHAF, gsm[r1*33 + n + 1], C2[mt][nt][3] + bb1);
            *(float2*)(outb + r0*32 + n) = o0;
            *(float2*)(outb + r1*32 + n) = o1;
        }
    }
}

extern "C" void kernel_launch(void* const* d_in, const int* in_sizes, int n_in,
                              void* d_out, int out_size) {
    const float* grid = (const float*)d_in[0];
    const float* pot  = (const float*)d_in[1];
    const float* W1   = (const float*)d_in[2];
    const float* b1   = (const float*)d_in[3];
    const float* W2   = (const float*)d_in[4];
    const float* b2   = (const float*)d_in[5];
    float* out = (float*)d_out;

    static bool attr_set = false;
    if (!attr_set) {
        cudaFuncSetAttribute(be_mma, cudaFuncAttributeMaxDynamicSharedMemorySize, SMEMSZ);
        attr_set = true;
    }
    be_mma<<<8192, 128, SMEMSZ>>>(grid, pot, W1, b1, W2, b2, out);
}